// round 14
// baseline (speedup 1.0000x reference)
#include <cuda_runtime.h>
#include <cuda_bf16.h>
#include <math.h>
#include <cstdint>

#define VV   8
#define HH   240
#define WWI  320
#define NP   (VV*HH*WWI)       // 614400
#define RESV 32
#define VN   (RESV*RESV*RESV)  // 32768
#define CE   62
#define BCAP 128               // bucket capacity per voxel (mean count ~18.75)

// ---------------- scratch (static device globals; no allocation) ----------------
static __device__ unsigned g_mn[3];
static __device__ unsigned g_mx[3];
static __device__ int      g_cnt[VN];
static __device__ int      g_bucket[(size_t)VN*BCAP];   // 16.8 MB
static __device__ __align__(16) __nv_bfloat16 g_Ehi[(size_t)VN*64];
static __device__ __align__(16) __nv_bfloat16 g_Elo[(size_t)VN*64];
static __device__ __align__(16) __nv_bfloat16 g_W1hi[256*64];
static __device__ __align__(16) __nv_bfloat16 g_W1lo[256*64];
static __device__ __align__(16) __nv_bfloat16 g_W2hi[256*256];
static __device__ __align__(16) __nv_bfloat16 g_W2lo[256*256];

// order-preserving float<->uint map
__device__ __forceinline__ unsigned fmapu(float f){
    unsigned u = __float_as_uint(f);
    return (u & 0x80000000u) ? ~u : (u | 0x80000000u);
}
__device__ __forceinline__ float funmap(unsigned u){
    return __uint_as_float((u & 0x80000000u) ? (u ^ 0x80000000u) : ~u);
}
__device__ __forceinline__ uint32_t smem_u32(const void* p){
    uint32_t a;
    asm("{ .reg .u64 t; cvta.to.shared.u64 t, %1; cvt.u32.u64 %0, t; }" : "=r"(a) : "l"(p));
    return a;
}

// vid computation — identical math to reference everywhere it is used
__device__ __forceinline__ int vox_id3(float p0, float p1, float p2){
    float mn0 = funmap(g_mn[0]), mn1 = funmap(g_mn[1]), mn2 = funmap(g_mn[2]);
    float vs0 = (funmap(g_mx[0]) - mn0) / 32.0f;
    float vs1 = (funmap(g_mx[1]) - mn1) / 32.0f;
    float vs2 = (funmap(g_mx[2]) - mn2) / 32.0f;
    int c0 = (int)floorf((p0 - mn0) / vs0);
    int c1 = (int)floorf((p1 - mn1) / vs1);
    int c2 = (int)floorf((p2 - mn2) / vs2);
    c0 = min(max(c0,0), RESV-1);
    c1 = min(max(c1,0), RESV-1);
    c2 = min(max(c2,0), RESV-1);
    return (c0*RESV + c1)*RESV + c2;
}

// ---------------- init ----------------
__global__ void k_init(){
    int i = blockIdx.x*blockDim.x + threadIdx.x;
    if (i < VN) g_cnt[i] = 0;
    if (i < 3){ g_mn[i] = 0xFFFFFFFFu; g_mx[i] = 0u; }
}

// ---------------- min/max over positions ----------------
__global__ void k_minmax(const float* __restrict__ pos){
    unsigned ln[3] = {0xFFFFFFFFu,0xFFFFFFFFu,0xFFFFFFFFu};
    unsigned lx[3] = {0u,0u,0u};
    int stride = gridDim.x*blockDim.x;
    for (int n = blockIdx.x*blockDim.x + threadIdx.x; n < NP; n += stride){
        #pragma unroll
        for (int c = 0; c < 3; c++){
            unsigned m = fmapu(pos[(size_t)n*3 + c]);
            ln[c] = min(ln[c], m);
            lx[c] = max(lx[c], m);
        }
    }
    #pragma unroll
    for (int o = 16; o; o >>= 1){
        #pragma unroll
        for (int c = 0; c < 3; c++){
            ln[c] = min(ln[c], __shfl_xor_sync(0xffffffffu, ln[c], o));
            lx[c] = max(lx[c], __shfl_xor_sync(0xffffffffu, lx[c], o));
        }
    }
    if ((threadIdx.x & 31) == 0){
        #pragma unroll
        for (int c = 0; c < 3; c++){
            atomicMin(&g_mn[c], ln[c]);
            atomicMax(&g_mx[c], lx[c]);
        }
    }
}

// ---------------- bin: direct bucket scatter (int indices, 4B writes) ----------------
__global__ void k_bin(const float* __restrict__ pos){
    int n = blockIdx.x*blockDim.x + threadIdx.x;
    if (n >= NP) return;
    int vid = vox_id3(pos[(size_t)n*3+0], pos[(size_t)n*3+1], pos[(size_t)n*3+2]);
    int p = atomicAdd(&g_cnt[vid], 1);
    if (p < BCAP) g_bucket[(size_t)vid*BCAP + p] = n;
}

// exact reference distance: rounded per-op, no FMA contraction
__device__ __forceinline__ float dist3(const float* __restrict__ pos, int id,
                                       float cx, float cy, float cz){
    float dx = __fadd_rn(pos[(size_t)id*3+0], -cx);
    float dy = __fadd_rn(pos[(size_t)id*3+1], -cy);
    float dz = __fadd_rn(pos[(size_t)id*3+2], -cz);
    return __fadd_rn(__fadd_rn(__fmul_rn(dx,dx), __fmul_rn(dy,dy)), __fmul_rn(dz,dz));
}

// ---------------- bilinear align_corners sample ----------------
__device__ __forceinline__ float bilin(const float* __restrict__ f, int vv, int C, int ch,
                                       int hs, int ws, int h, int w){
    float ry = (float)((double)(hs-1) / (double)(HH-1));
    float rx = (float)((double)(ws-1) / (double)(WWI-1));
    float ys = (float)h * ry;
    float xs = (float)w * rx;
    int y0 = (int)floorf(ys), x0 = (int)floorf(xs);
    int y1 = min(y0+1, hs-1), x1 = min(x0+1, ws-1);
    float wy = ys - (float)y0;
    float wx = xs - (float)x0;
    const float* base = f + ((size_t)(vv*C + ch)) * hs * ws;
    float a = base[y0*ws + x0];
    float b = base[y0*ws + x1];
    float c = base[y1*ws + x0];
    float d = base[y1*ws + x1];
    return (a*(1.f-wx) + b*wx)*(1.f-wy) + (c*(1.f-wx) + d*wx)*wy;
}

// ============ FUSED select+gather: ONE WARP PER VOXEL ============
// Phase 1 (select): key-only bitonic sort + static-origin ordered sum + parallel argmin
//                   (bitwise identical to validated R13 logic).
// Phase 2 (gather): same warp immediately gathers features for its midx.
__global__ void k_selgather(const float* __restrict__ pos, const float* __restrict__ pdir,
                            const float* __restrict__ rgb, const float* __restrict__ f1,
                            const float* __restrict__ f2,  const float* __restrict__ f3,
                            float* __restrict__ out){
    int gw   = (blockIdx.x*blockDim.x + threadIdx.x) >> 5;
    int lane = threadIdx.x & 31;
    if (gw >= VN) return;
    int v = gw;
    int c = g_cnt[v];
    const int* bkt = &g_bucket[(size_t)v*BCAP];
    const unsigned F = 0xffffffffu;

    // ---------- phase 1: select ----------
    int m = 0x7FFFFFFF;   // voxel's chosen point index
    if (c > 0 && c <= 32){
        int   id = (lane < c) ? bkt[lane] : 0x7FFFFFFF;
        float px = 0.f, py = 0.f, pz = 0.f;
        if (lane < c){
            px = pos[(size_t)id*3+0];
            py = pos[(size_t)id*3+1];
            pz = pos[(size_t)id*3+2];
        }
        // key-only bitonic sort ascending: key = (id<<5)|lane (id < 2^20). pads sink to top.
        unsigned key = (lane < c) ? (((unsigned)id << 5) | (unsigned)lane) : 0xFFFFFFFFu;
        #pragma unroll
        for (int k = 2; k <= 32; k <<= 1){
            #pragma unroll
            for (int j = k >> 1; j > 0; j >>= 1){
                unsigned ok = __shfl_xor_sync(F, key, j);
                bool up    = ((lane & k) == 0);
                bool lower = ((lane & j) == 0);
                if ((ok < key) == (lower == up)) key = ok;
            }
        }
        // pre-permute into rank order, then static-origin strict left-to-right sum
        int o = (int)(key & 31u);
        float qx = __shfl_sync(F, px, o);
        float qy = __shfl_sync(F, py, o);
        float qz = __shfl_sync(F, pz, o);
        float sx = 0.f, sy = 0.f, sz = 0.f;
        #pragma unroll
        for (int i = 0; i < 32; i++){
            float xx = __shfl_sync(F, qx, i);
            float yy = __shfl_sync(F, qy, i);
            float zz = __shfl_sync(F, qz, i);
            if (i < c){
                sx = __fadd_rn(sx, xx);
                sy = __fadd_rn(sy, yy);
                sz = __fadd_rn(sz, zz);
            }
        }
        float den = (float)c;
        float cx = sx/den, cy = sy/den, cz = sz/den;
        // per-lane exact distance; parallel min with smaller-id tie-break
        float dx = __fadd_rn(px, -cx);
        float dy = __fadd_rn(py, -cy);
        float dz = __fadd_rn(pz, -cz);
        float d  = __fadd_rn(__fadd_rn(__fmul_rn(dx,dx), __fmul_rn(dy,dy)), __fmul_rn(dz,dz));
        float bd = (lane < c) ? d  : __int_as_float(0x7F800000);
        int   bi = (lane < c) ? id : 0x7FFFFFFF;
        #pragma unroll
        for (int oo = 16; oo; oo >>= 1){
            float od = __shfl_xor_sync(F, bd, oo);
            int   oi = __shfl_xor_sync(F, bi, oo);
            if (od < bd || (od == bd && oi < bi)){ bd = od; bi = oi; }
        }
        m = bi;   // all lanes hold the result after the xor reduction
    } else if (c > 32){
        // rare tails on lane 0, then broadcast
        int midx = 0x7FFFFFFF;
        if (lane == 0){
            float sx = 0.f, sy = 0.f, sz = 0.f;
            if (c <= 96){
                int a[96];
                for (int i = 0; i < c; i++) a[i] = bkt[i];
                for (int i = 1; i < c; i++){
                    int key = a[i];
                    int j = i-1;
                    while (j >= 0 && a[j] > key){ a[j+1] = a[j]; j--; }
                    a[j+1] = key;
                }
                for (int i = 0; i < c; i++){
                    int id = a[i];
                    sx = __fadd_rn(sx, pos[(size_t)id*3+0]);
                    sy = __fadd_rn(sy, pos[(size_t)id*3+1]);
                    sz = __fadd_rn(sz, pos[(size_t)id*3+2]);
                }
                float den = (float)c;
                float cx = sx/den, cy = sy/den, cz = sz/den;
                float dmin = __int_as_float(0x7F800000);
                for (int i = 0; i < c; i++){
                    float d = dist3(pos, a[i], cx, cy, cz);
                    if (d < dmin){ dmin = d; midx = a[i]; }
                }
            } else if (c <= BCAP){
                int prev = -1;
                for (int it = 0; it < c; it++){
                    int best = 0x7FFFFFFF;
                    for (int j = 0; j < c; j++){
                        int id = bkt[j];
                        if (id > prev && id < best) best = id;
                    }
                    prev = best;
                    sx = __fadd_rn(sx, pos[(size_t)best*3+0]);
                    sy = __fadd_rn(sy, pos[(size_t)best*3+1]);
                    sz = __fadd_rn(sz, pos[(size_t)best*3+2]);
                }
                float den = (float)c;
                float cx = sx/den, cy = sy/den, cz = sz/den;
                float dmin = __int_as_float(0x7F800000);
                for (int j = 0; j < c; j++){
                    float d = dist3(pos, bkt[j], cx, cy, cz);
                    if (d < dmin){ dmin = d; midx = bkt[j]; }
                    else if (d == dmin) midx = min(midx, bkt[j]);
                }
            } else {
                // bucket overflow (P < 1e-60): full recompute scan in index order
                for (int n = 0; n < NP; n++){
                    if (vox_id3(pos[(size_t)n*3+0], pos[(size_t)n*3+1], pos[(size_t)n*3+2]) == v){
                        sx = __fadd_rn(sx, pos[(size_t)n*3+0]);
                        sy = __fadd_rn(sy, pos[(size_t)n*3+1]);
                        sz = __fadd_rn(sz, pos[(size_t)n*3+2]);
                    }
                }
                float den = (float)c;
                float cx = sx/den, cy = sy/den, cz = sz/den;
                float dmin = __int_as_float(0x7F800000);
                for (int n = 0; n < NP; n++){
                    if (vox_id3(pos[(size_t)n*3+0], pos[(size_t)n*3+1], pos[(size_t)n*3+2]) == v){
                        float d = dist3(pos, n, cx, cy, cz);
                        if (d < dmin){ dmin = d; midx = n; }
                    }
                }
            }
        }
        m = __shfl_sync(F, midx, 0);
    }
    // empty voxel (c==0): m stays INT_MAX -> mapped to 0 below (matches reference)

    // ---------- phase 2: gather ----------
    if (m < 0 || m >= NP) m = 0;
    int vv  = m / (HH*WWI);
    int rem = m - vv*HH*WWI;
    int h   = rem / WWI;
    int w   = rem - h*WWI;

    float* out_pos = out + (size_t)VN*256;
    float* out_col = out_pos + (size_t)VN*3;
    float* out_dir = out_col + (size_t)VN*3;

    if (lane < 3){
        out_pos[gw*3 + lane] = pos[(size_t)m*3 + lane];
        out_dir[gw*3 + lane] = pdir[(size_t)m*3 + lane];
        out_col[gw*3 + lane] = rgb[((size_t)(vv*3 + lane)*HH + h)*WWI + w];
    }
    #pragma unroll
    for (int rd = 0; rd < 2; rd++){
        int ch = lane + rd*32;
        float val;
        if      (ch < 3)  val = rgb[((size_t)(vv*3 + ch)*HH + h)*WWI + w];
        else if (ch < 11) val = bilin(f1, vv,  8, ch-3,  120, 160, h, w);
        else if (ch < 27) val = bilin(f2, vv, 16, ch-11,  60,  80, h, w);
        else if (ch < 59) val = bilin(f3, vv, 32, ch-27,  30,  40, h, w);
        else if (ch < 62) val = pdir[(size_t)m*3 + (ch-59)];
        else              val = 0.0f;
        __nv_bfloat16 hv = __float2bfloat16(val);
        g_Ehi[(size_t)gw*64 + ch] = hv;
        g_Elo[(size_t)gw*64 + ch] = __float2bfloat16(val - __bfloat162float(hv));
    }
}

// ---------------- convert + transpose weights to bf16 hi/lo, [N][K] K-major ----------------
__global__ void k_cvtW(const float* __restrict__ W1, const float* __restrict__ W2){
    int i = blockIdx.x*blockDim.x + threadIdx.x;
    if (i < 256*64){
        int n = i >> 6, k = i & 63;
        float w = (k < CE) ? W1[(size_t)k*256 + n] : 0.0f;
        __nv_bfloat16 hv = __float2bfloat16(w);
        g_W1hi[i] = hv;
        g_W1lo[i] = __float2bfloat16(w - __bfloat162float(hv));
    } else if (i < 256*64 + 256*256){
        int j = i - 256*64;
        int n = j >> 8, k = j & 255;
        float w = W2[(size_t)k*256 + n];
        __nv_bfloat16 hv = __float2bfloat16(w);
        g_W2hi[j] = hv;
        g_W2lo[j] = __float2bfloat16(w - __bfloat162float(hv));
    }
}

// ================= fused 2-layer MLP via HMMA (mma.sync bf16, 3-term split) =================
// Block: 128 rows x 256 cols, 8 warps as 2(m) x 4(n), each warp a 64x64 tile.
#define SB_W1HI 0
#define SB_W1LO 36864
#define SB_EHI  73728
#define SB_ELO  92160
#define SB_HHI  0        // reuses W1/E region after stage 1
#define SB_HLO  67584
#define SB_W2HI 135168
#define SB_W2LO 172032
#define SB_B1   208896
#define SB_B2   209920
#define SMEM_TOT 210944

#define LDSM_X4(r0,r1,r2,r3, addr) \
    asm volatile("ldmatrix.sync.aligned.m8n8.x4.shared.b16 {%0,%1,%2,%3}, [%4];" \
        : "=r"(r0), "=r"(r1), "=r"(r2), "=r"(r3) : "r"(addr))

#define MMA_BF16(d, a0,a1,a2,a3, b0,b1) \
    asm volatile("mma.sync.aligned.m16n8k16.row.col.f32.bf16.bf16.f32 " \
        "{%0,%1,%2,%3}, {%4,%5,%6,%7}, {%8,%9}, {%0,%1,%2,%3};" \
        : "+f"((d)[0]), "+f"((d)[1]), "+f"((d)[2]), "+f"((d)[3]) \
        : "r"(a0), "r"(a1), "r"(a2), "r"(a3), "r"(b0), "r"(b1))

__global__ void __launch_bounds__(256, 1) k_mlp(const float* __restrict__ b1,
                                                const float* __restrict__ b2,
                                                float* __restrict__ out){
    extern __shared__ char smc[];
    uint32_t sb = smem_u32(smc);
    int tid = threadIdx.x, lane = tid & 31, wid = tid >> 5;
    int wm = wid >> 2, wn = wid & 3;       // 2 x 4 warp grid
    int row0 = blockIdx.x * 128;
    int q = lane & 7, t = lane >> 3;
    int g = lane >> 2, tq = lane & 3;

    ((float*)(smc + SB_B1))[tid] = b1[tid];
    ((float*)(smc + SB_B2))[tid] = b2[tid];

    for (int i = tid; i < 256*8; i += 256){
        int r = i >> 3, j = i & 7;
        *(uint4*)(smc + SB_W1HI + r*144 + j*16) = *(const uint4*)(g_W1hi + (size_t)r*64 + j*8);
        *(uint4*)(smc + SB_W1LO + r*144 + j*16) = *(const uint4*)(g_W1lo + (size_t)r*64 + j*8);
    }
    for (int i = tid; i < 128*8; i += 256){
        int r = i >> 3, j = i & 7;
        *(uint4*)(smc + SB_EHI + r*144 + j*16) = *(const uint4*)(g_Ehi + (size_t)(row0+r)*64 + j*8);
        *(uint4*)(smc + SB_ELO + r*144 + j*16) = *(const uint4*)(g_Elo + (size_t)(row0+r)*64 + j*8);
    }
    __syncthreads();

    float acc[4][8][4];
    #pragma unroll
    for (int mi = 0; mi < 4; mi++)
        #pragma unroll
        for (int ni = 0; ni < 8; ni++)
            #pragma unroll
            for (int e = 0; e < 4; e++) acc[mi][ni][e] = 0.0f;

    uint32_t laneA144 = (uint32_t)(((t & 1)*8 + q)*144 + (t >> 1)*16);
    uint32_t laneA528 = (uint32_t)(((t & 1)*8 + q)*528 + (t >> 1)*16);
    uint32_t laneB144 = (uint32_t)(((t >> 1)*8 + q)*144 + (t & 1)*16);

    // ---- stage 1: K = 64 ----
    {
        uint32_t aHi = sb + SB_EHI  + (uint32_t)(wm*64)*144 + laneA144;
        uint32_t aLo = sb + SB_ELO  + (uint32_t)(wm*64)*144 + laneA144;
        uint32_t bHi = sb + SB_W1HI + (uint32_t)(wn*64)*144 + laneB144;
        uint32_t bLo = sb + SB_W1LO + (uint32_t)(wn*64)*144 + laneB144;
        for (int kk = 0; kk < 4; kk++){
            uint32_t k0b = kk*32;
            uint32_t bh[8][2], bl[8][2];
            #pragma unroll
            for (int nj = 0; nj < 4; nj++){
                LDSM_X4(bh[2*nj][0], bh[2*nj][1], bh[2*nj+1][0], bh[2*nj+1][1],
                        bHi + (uint32_t)(nj*16)*144 + k0b);
                LDSM_X4(bl[2*nj][0], bl[2*nj][1], bl[2*nj+1][0], bl[2*nj+1][1],
                        bLo + (uint32_t)(nj*16)*144 + k0b);
            }
            #pragma unroll
            for (int mi = 0; mi < 4; mi++){
                uint32_t a0,a1,a2,a3;
                LDSM_X4(a0,a1,a2,a3, aHi + (uint32_t)(mi*16)*144 + k0b);
                #pragma unroll
                for (int ni = 0; ni < 8; ni++){
                    MMA_BF16(acc[mi][ni], a0,a1,a2,a3, bh[ni][0], bh[ni][1]);
                    MMA_BF16(acc[mi][ni], a0,a1,a2,a3, bl[ni][0], bl[ni][1]);
                }
                LDSM_X4(a0,a1,a2,a3, aLo + (uint32_t)(mi*16)*144 + k0b);
                #pragma unroll
                for (int ni = 0; ni < 8; ni++)
                    MMA_BF16(acc[mi][ni], a0,a1,a2,a3, bh[ni][0], bh[ni][1]);
            }
        }
    }
    __syncthreads();   // all warps done reading W1/E before H overwrites the region

    // ---- epilogue 1: relu(acc + b1) -> H hi/lo in smem, zero acc ----
    {
        const float* b1s = (const float*)(smc + SB_B1);
        #pragma unroll
        for (int mi = 0; mi < 4; mi++){
            int r0 = wm*64 + mi*16 + g;
            #pragma unroll
            for (int ni = 0; ni < 8; ni++){
                int col = wn*64 + ni*8 + tq*2;
                float bc0 = b1s[col], bc1 = b1s[col+1];
                #pragma unroll
                for (int half = 0; half < 2; half++){
                    int r = r0 + half*8;
                    float v0 = fmaxf(acc[mi][ni][half*2+0] + bc0, 0.0f);
                    float v1 = fmaxf(acc[mi][ni][half*2+1] + bc1, 0.0f);
                    __nv_bfloat16 h0 = __float2bfloat16(v0);
                    __nv_bfloat16 h1 = __float2bfloat16(v1);
                    __nv_bfloat162 hp; hp.x = h0; hp.y = h1;
                    __nv_bfloat162 lp;
                    lp.x = __float2bfloat16(v0 - __bfloat162float(h0));
                    lp.y = __float2bfloat16(v1 - __bfloat162float(h1));
                    *(__nv_bfloat162*)(smc + SB_HHI + r*528 + col*2) = hp;
                    *(__nv_bfloat162*)(smc + SB_HLO + r*528 + col*2) = lp;
                    acc[mi][ni][half*2+0] = 0.0f;
                    acc[mi][ni][half*2+1] = 0.0f;
                }
            }
        }
    }

    // ---- stage 2: K = 256 in 4 chunks; A = H (smem), B = W2 (streamed) ----
    {
        uint32_t aHi = sb + SB_HHI + (uint32_t)(wm*64)*528 + laneA528;
        uint32_t aLo = sb + SB_HLO + (uint32_t)(wm*64)*528 + laneA528;
        uint32_t bHi = sb + SB_W2HI + (uint32_t)(wn*64)*144 + laneB144;
        uint32_t bLo = sb + SB_W2LO + (uint32_t)(wn*64)*144 + laneB144;
        for (int kc = 0; kc < 4; kc++){
            __syncthreads();
            for (int i = tid; i < 256*8; i += 256){
                int r = i >> 3, j = i & 7;
                *(uint4*)(smc + SB_W2HI + r*144 + j*16) =
                    *(const uint4*)(g_W2hi + (size_t)r*256 + kc*64 + j*8);
                *(uint4*)(smc + SB_W2LO + r*144 + j*16) =
                    *(const uint4*)(g_W2lo + (size_t)r*256 + kc*64 + j*8);
            }
            __syncthreads();
            for (int kk = 0; kk < 4; kk++){
                uint32_t k0A = (uint32_t)(kc*64 + kk*16)*2;
                uint32_t k0B = kk*32;
                uint32_t bh[8][2], bl[8][2];
                #pragma unroll
                for (int nj = 0; nj < 4; nj++){
                    LDSM_X4(bh[2*nj][0], bh[2*nj][1], bh[2*nj+1][0], bh[2*nj+1][1],
                            bHi + (uint32_t)(nj*16)*144 + k0B);
                    LDSM_X4(bl[2*nj][0], bl[2*nj][1], bl[2*nj+1][0], bl[2*nj+1][1],
                            bLo + (uint32_t)(nj*16)*144 + k0B);
                }
                #pragma unroll
                for (int mi = 0; mi < 4; mi++){
                    uint32_t a0,a1,a2,a3;
                    LDSM_X4(a0,a1,a2,a3, aHi + (uint32_t)(mi*16)*528 + k0A);
                    #pragma unroll
                    for (int ni = 0; ni < 8; ni++){
                        MMA_BF16(acc[mi][ni], a0,a1,a2,a3, bh[ni][0], bh[ni][1]);
                        MMA_BF16(acc[mi][ni], a0,a1,a2,a3, bl[ni][0], bl[ni][1]);
                    }
                    LDSM_X4(a0,a1,a2,a3, aLo + (uint32_t)(mi*16)*528 + k0A);
                    #pragma unroll
                    for (int ni = 0; ni < 8; ni++)
                        MMA_BF16(acc[mi][ni], a0,a1,a2,a3, bh[ni][0], bh[ni][1]);
                }
            }
        }
    }

    // ---- epilogue 2: out = acc + b2 ----
    {
        const float* b2s = (const float*)(smc + SB_B2);
        #pragma unroll
        for (int mi = 0; mi < 4; mi++){
            int r0 = row0 + wm*64 + mi*16 + g;
            #pragma unroll
            for (int ni = 0; ni < 8; ni++){
                int col = wn*64 + ni*8 + tq*2;
                float bc0 = b2s[col], bc1 = b2s[col+1];
                #pragma unroll
                for (int half = 0; half < 2; half++){
                    int r = r0 + half*8;
                    float2 o;
                    o.x = acc[mi][ni][half*2+0] + bc0;
                    o.y = acc[mi][ni][half*2+1] + bc1;
                    *(float2*)&out[(size_t)r*256 + col] = o;
                }
            }
        }
    }
}

// ---------------- launcher ----------------
extern "C" void kernel_launch(void* const* d_in, const int* in_sizes, int n_in,
                              void* d_out, int out_size){
    const float* rgb  = (const float*)d_in[0];
    const float* f1   = (const float*)d_in[1];
    const float* f2   = (const float*)d_in[2];
    const float* f3   = (const float*)d_in[3];
    const float* pos  = (const float*)d_in[4];
    const float* pdir = (const float*)d_in[5];
    const float* W1   = (const float*)d_in[6];
    const float* b1   = (const float*)d_in[7];
    const float* W2   = (const float*)d_in[8];
    const float* b2   = (const float*)d_in[9];
    float* out = (float*)d_out;

    cudaFuncSetAttribute(k_mlp, cudaFuncAttributeMaxDynamicSharedMemorySize, SMEM_TOT);

    k_init     <<<(VN+255)/256, 256>>>();
    k_minmax   <<<256, 256>>>(pos);
    k_bin      <<<NP/256, 256>>>(pos);           // direct bucket scatter
    k_selgather<<<VN*32/256, 256>>>(pos, pdir, rgb, f1, f2, f3, out);  // fused select+gather
    k_cvtW     <<<320, 256>>>(W1, W2);
    k_mlp      <<<VN/128, 256, SMEM_TOT>>>(b1, b2, out);
}

// round 15
// speedup vs baseline: 1.0447x; 1.0447x over previous
#include <cuda_runtime.h>
#include <cuda_bf16.h>
#include <math.h>
#include <cstdint>

#define VV   8
#define HH   240
#define WWI  320
#define NP   (VV*HH*WWI)       // 614400
#define RESV 32
#define VN   (RESV*RESV*RESV)  // 32768
#define CE   62
#define BCAP 128               // bucket capacity per voxel (mean count ~18.75)

// ---------------- scratch (static device globals; no allocation) ----------------
static __device__ unsigned g_mn[3];
static __device__ unsigned g_mx[3];
static __device__ int      g_cnt[VN];
static __device__ int      g_bucket[(size_t)VN*BCAP];   // 16.8 MB
static __device__ int      g_midx[VN];
static __device__ __align__(16) __nv_bfloat16 g_Ehi[(size_t)VN*64];
static __device__ __align__(16) __nv_bfloat16 g_Elo[(size_t)VN*64];
static __device__ __align__(16) __nv_bfloat16 g_W1hi[256*64];
static __device__ __align__(16) __nv_bfloat16 g_W1lo[256*64];
static __device__ __align__(16) __nv_bfloat16 g_W2hi[256*256];
static __device__ __align__(16) __nv_bfloat16 g_W2lo[256*256];

// order-preserving float<->uint map
__device__ __forceinline__ unsigned fmapu(float f){
    unsigned u = __float_as_uint(f);
    return (u & 0x80000000u) ? ~u : (u | 0x80000000u);
}
__device__ __forceinline__ float funmap(unsigned u){
    return __uint_as_float((u & 0x80000000u) ? (u ^ 0x80000000u) : ~u);
}
__device__ __forceinline__ uint32_t smem_u32(const void* p){
    uint32_t a;
    asm("{ .reg .u64 t; cvta.to.shared.u64 t, %1; cvt.u32.u64 %0, t; }" : "=r"(a) : "l"(p));
    return a;
}

// vid computation — identical math to reference everywhere it is used
__device__ __forceinline__ int vox_id3(float p0, float p1, float p2){
    float mn0 = funmap(g_mn[0]), mn1 = funmap(g_mn[1]), mn2 = funmap(g_mn[2]);
    float vs0 = (funmap(g_mx[0]) - mn0) / 32.0f;
    float vs1 = (funmap(g_mx[1]) - mn1) / 32.0f;
    float vs2 = (funmap(g_mx[2]) - mn2) / 32.0f;
    int c0 = (int)floorf((p0 - mn0) / vs0);
    int c1 = (int)floorf((p1 - mn1) / vs1);
    int c2 = (int)floorf((p2 - mn2) / vs2);
    c0 = min(max(c0,0), RESV-1);
    c1 = min(max(c1,0), RESV-1);
    c2 = min(max(c2,0), RESV-1);
    return (c0*RESV + c1)*RESV + c2;
}

// ---------------- init + weight convert (fused, independent early work) ----------------
__global__ void k_init_cvt(const float* __restrict__ W1, const float* __restrict__ W2){
    int i = blockIdx.x*blockDim.x + threadIdx.x;
    if (i < VN) g_cnt[i] = 0;
    if (i < 3){ g_mn[i] = 0xFFFFFFFFu; g_mx[i] = 0u; }
    if (i < 256*64){
        int n = i >> 6, k = i & 63;
        float w = (k < CE) ? W1[(size_t)k*256 + n] : 0.0f;
        __nv_bfloat16 hv = __float2bfloat16(w);
        g_W1hi[i] = hv;
        g_W1lo[i] = __float2bfloat16(w - __bfloat162float(hv));
    }
    if (i < 256*256){
        int n = i >> 8, k = i & 255;
        float w = W2[(size_t)k*256 + n];
        __nv_bfloat16 hv = __float2bfloat16(w);
        g_W2hi[i] = hv;
        g_W2lo[i] = __float2bfloat16(w - __bfloat162float(hv));
    }
}

// ---------------- min/max over positions ----------------
__global__ void k_minmax(const float* __restrict__ pos){
    unsigned ln[3] = {0xFFFFFFFFu,0xFFFFFFFFu,0xFFFFFFFFu};
    unsigned lx[3] = {0u,0u,0u};
    int stride = gridDim.x*blockDim.x;
    for (int n = blockIdx.x*blockDim.x + threadIdx.x; n < NP; n += stride){
        #pragma unroll
        for (int c = 0; c < 3; c++){
            unsigned m = fmapu(pos[(size_t)n*3 + c]);
            ln[c] = min(ln[c], m);
            lx[c] = max(lx[c], m);
        }
    }
    #pragma unroll
    for (int o = 16; o; o >>= 1){
        #pragma unroll
        for (int c = 0; c < 3; c++){
            ln[c] = min(ln[c], __shfl_xor_sync(0xffffffffu, ln[c], o));
            lx[c] = max(lx[c], __shfl_xor_sync(0xffffffffu, lx[c], o));
        }
    }
    if ((threadIdx.x & 31) == 0){
        #pragma unroll
        for (int c = 0; c < 3; c++){
            atomicMin(&g_mn[c], ln[c]);
            atomicMax(&g_mx[c], lx[c]);
        }
    }
}

// ---------------- bin: direct bucket scatter (int indices, 4B writes) ----------------
__global__ void k_bin(const float* __restrict__ pos){
    int n = blockIdx.x*blockDim.x + threadIdx.x;
    if (n >= NP) return;
    int vid = vox_id3(pos[(size_t)n*3+0], pos[(size_t)n*3+1], pos[(size_t)n*3+2]);
    int p = atomicAdd(&g_cnt[vid], 1);
    if (p < BCAP) g_bucket[(size_t)vid*BCAP + p] = n;
}

// exact reference distance: rounded per-op, no FMA contraction
__device__ __forceinline__ float dist3(const float* __restrict__ pos, int id,
                                       float cx, float cy, float cz){
    float dx = __fadd_rn(pos[(size_t)id*3+0], -cx);
    float dy = __fadd_rn(pos[(size_t)id*3+1], -cy);
    float dz = __fadd_rn(pos[(size_t)id*3+2], -cz);
    return __fadd_rn(__fadd_rn(__fmul_rn(dx,dx), __fmul_rn(dy,dy)), __fmul_rn(dz,dz));
}

// ---------------- select: ONE WARP PER VOXEL, key sort + c-bounded uniform-origin sum ----------------
__global__ void k_select(const float* __restrict__ pos){
    int gw   = (blockIdx.x*blockDim.x + threadIdx.x) >> 5;
    int lane = threadIdx.x & 31;
    if (gw >= VN) return;
    int v = gw;
    int c = g_cnt[v];
    const int* bkt = &g_bucket[(size_t)v*BCAP];
    if (c == 0){ if (lane == 0) g_midx[v] = 0x7FFFFFFF; return; }

    const unsigned F = 0xffffffffu;

    if (c <= 32){
        int   id = (lane < c) ? bkt[lane] : 0x7FFFFFFF;
        float px = 0.f, py = 0.f, pz = 0.f;
        if (lane < c){
            px = pos[(size_t)id*3+0];
            py = pos[(size_t)id*3+1];
            pz = pos[(size_t)id*3+2];
        }
        // key-only bitonic sort ascending: key = (id<<5)|lane (id < 2^20). pads sink to top.
        unsigned key = (lane < c) ? (((unsigned)id << 5) | (unsigned)lane) : 0xFFFFFFFFu;
        #pragma unroll
        for (int k = 2; k <= 32; k <<= 1){
            #pragma unroll
            for (int j = k >> 1; j > 0; j >>= 1){
                unsigned ok = __shfl_xor_sync(F, key, j);
                bool up    = ((lane & k) == 0);
                bool lower = ((lane & j) == 0);
                if ((ok < key) == (lower == up)) key = ok;
            }
        }
        // pre-permute data into rank order: lane i holds rank-i point's position
        int o = (int)(key & 31u);
        float qx = __shfl_sync(F, px, o);
        float qy = __shfl_sync(F, py, o);
        float qz = __shfl_sync(F, pz, o);
        // strict left-to-right fp32 sum over ascending-id order (replicates XLA CPU scatter).
        // Loop-counter shfl origins: warp-uniform, no data dependency; only c (~19) iterations.
        float sx = 0.f, sy = 0.f, sz = 0.f;
        for (int i = 0; i < c; i++){
            float xx = __shfl_sync(F, qx, i);
            float yy = __shfl_sync(F, qy, i);
            float zz = __shfl_sync(F, qz, i);
            sx = __fadd_rn(sx, xx);
            sy = __fadd_rn(sy, yy);
            sz = __fadd_rn(sz, zz);
        }
        float den = (float)c;
        float cx = sx/den, cy = sy/den, cz = sz/den;
        // per-lane exact distance on own (unsorted) data; parallel min, smaller-id tie-break
        float dx = __fadd_rn(px, -cx);
        float dy = __fadd_rn(py, -cy);
        float dz = __fadd_rn(pz, -cz);
        float d  = __fadd_rn(__fadd_rn(__fmul_rn(dx,dx), __fmul_rn(dy,dy)), __fmul_rn(dz,dz));
        float bd = (lane < c) ? d  : __int_as_float(0x7F800000);
        int   bi = (lane < c) ? id : 0x7FFFFFFF;
        #pragma unroll
        for (int oo = 16; oo; oo >>= 1){
            float od = __shfl_xor_sync(F, bd, oo);
            int   oi = __shfl_xor_sync(F, bi, oo);
            if (od < bd || (od == bd && oi < bi)){ bd = od; bi = oi; }
        }
        if (lane == 0) g_midx[v] = bi;
        return;
    }

    // rare tails: lane 0 runs the validated serial paths
    if (lane != 0) return;
    float sx = 0.f, sy = 0.f, sz = 0.f;
    int midx = 0x7FFFFFFF;
    if (c <= 96){
        int a[96];
        for (int i = 0; i < c; i++) a[i] = bkt[i];
        for (int i = 1; i < c; i++){
            int key = a[i];
            int j = i-1;
            while (j >= 0 && a[j] > key){ a[j+1] = a[j]; j--; }
            a[j+1] = key;
        }
        for (int i = 0; i < c; i++){
            int id = a[i];
            sx = __fadd_rn(sx, pos[(size_t)id*3+0]);
            sy = __fadd_rn(sy, pos[(size_t)id*3+1]);
            sz = __fadd_rn(sz, pos[(size_t)id*3+2]);
        }
        float den = (float)c;
        float cx = sx/den, cy = sy/den, cz = sz/den;
        float dmin = __int_as_float(0x7F800000);
        for (int i = 0; i < c; i++){
            float d = dist3(pos, a[i], cx, cy, cz);
            if (d < dmin){ dmin = d; midx = a[i]; }
        }
    } else if (c <= BCAP){
        int prev = -1;
        for (int it = 0; it < c; it++){
            int best = 0x7FFFFFFF;
            for (int j = 0; j < c; j++){
                int id = bkt[j];
                if (id > prev && id < best) best = id;
            }
            prev = best;
            sx = __fadd_rn(sx, pos[(size_t)best*3+0]);
            sy = __fadd_rn(sy, pos[(size_t)best*3+1]);
            sz = __fadd_rn(sz, pos[(size_t)best*3+2]);
        }
        float den = (float)c;
        float cx = sx/den, cy = sy/den, cz = sz/den;
        float dmin = __int_as_float(0x7F800000);
        for (int j = 0; j < c; j++){
            float d = dist3(pos, bkt[j], cx, cy, cz);
            if (d < dmin){ dmin = d; midx = bkt[j]; }
            else if (d == dmin) midx = min(midx, bkt[j]);
        }
    } else {
        // bucket overflow (P < 1e-60): full recompute scan in index order
        for (int n = 0; n < NP; n++){
            if (vox_id3(pos[(size_t)n*3+0], pos[(size_t)n*3+1], pos[(size_t)n*3+2]) == v){
                sx = __fadd_rn(sx, pos[(size_t)n*3+0]);
                sy = __fadd_rn(sy, pos[(size_t)n*3+1]);
                sz = __fadd_rn(sz, pos[(size_t)n*3+2]);
            }
        }
        float den = (float)c;
        float cx = sx/den, cy = sy/den, cz = sz/den;
        float dmin = __int_as_float(0x7F800000);
        for (int n = 0; n < NP; n++){
            if (vox_id3(pos[(size_t)n*3+0], pos[(size_t)n*3+1], pos[(size_t)n*3+2]) == v){
                float d = dist3(pos, n, cx, cy, cz);
                if (d < dmin){ dmin = d; midx = n; }
            }
        }
    }
    g_midx[v] = midx;
}

// ---------------- bilinear align_corners sample ----------------
__device__ __forceinline__ float bilin(const float* __restrict__ f, int vv, int C, int ch,
                                       int hs, int ws, int h, int w){
    float ry = (float)((double)(hs-1) / (double)(HH-1));
    float rx = (float)((double)(ws-1) / (double)(WWI-1));
    float ys = (float)h * ry;
    float xs = (float)w * rx;
    int y0 = (int)floorf(ys), x0 = (int)floorf(xs);
    int y1 = min(y0+1, hs-1), x1 = min(x0+1, ws-1);
    float wy = ys - (float)y0;
    float wx = xs - (float)x0;
    const float* base = f + ((size_t)(vv*C + ch)) * hs * ws;
    float a = base[y0*ws + x0];
    float b = base[y0*ws + x1];
    float c = base[y1*ws + x0];
    float d = base[y1*ws + x1];
    return (a*(1.f-wx) + b*wx)*(1.f-wy) + (c*(1.f-wx) + d*wx)*wy;
}

// ---------------- gather: E as bf16 hi/lo + pos/color/dir outputs ----------------
__global__ void k_gather(const float* __restrict__ rgb, const float* __restrict__ f1,
                         const float* __restrict__ f2,  const float* __restrict__ f3,
                         const float* __restrict__ pos, const float* __restrict__ pdir,
                         float* __restrict__ out){
    int gw   = (blockIdx.x*blockDim.x + threadIdx.x) >> 5;
    int lane = threadIdx.x & 31;
    if (gw >= VN) return;
    int m = g_midx[gw];
    if (m < 0 || m >= NP) m = 0;
    int vv  = m / (HH*WWI);
    int rem = m - vv*HH*WWI;
    int h   = rem / WWI;
    int w   = rem - h*WWI;

    float* out_pos = out + (size_t)VN*256;
    float* out_col = out_pos + (size_t)VN*3;
    float* out_dir = out_col + (size_t)VN*3;

    if (lane < 3){
        out_pos[gw*3 + lane] = pos[(size_t)m*3 + lane];
        out_dir[gw*3 + lane] = pdir[(size_t)m*3 + lane];
        out_col[gw*3 + lane] = rgb[((size_t)(vv*3 + lane)*HH + h)*WWI + w];
    }
    for (int ch = lane; ch < 64; ch += 32){
        float val;
        if      (ch < 3)  val = rgb[((size_t)(vv*3 + ch)*HH + h)*WWI + w];
        else if (ch < 11) val = bilin(f1, vv,  8, ch-3,  120, 160, h, w);
        else if (ch < 27) val = bilin(f2, vv, 16, ch-11,  60,  80, h, w);
        else if (ch < 59) val = bilin(f3, vv, 32, ch-27,  30,  40, h, w);
        else if (ch < 62) val = pdir[(size_t)m*3 + (ch-59)];
        else              val = 0.0f;
        __nv_bfloat16 hv = __float2bfloat16(val);
        g_Ehi[(size_t)gw*64 + ch] = hv;
        g_Elo[(size_t)gw*64 + ch] = __float2bfloat16(val - __bfloat162float(hv));
    }
}

// ================= fused 2-layer MLP via HMMA (mma.sync bf16, 3-term split) =================
// Block: 128 rows x 256 cols, 8 warps as 2(m) x 4(n), each warp a 64x64 tile.
#define SB_W1HI 0
#define SB_W1LO 36864
#define SB_EHI  73728
#define SB_ELO  92160
#define SB_HHI  0        // reuses W1/E region after stage 1
#define SB_HLO  67584
#define SB_W2HI 135168
#define SB_W2LO 172032
#define SB_B1   208896
#define SB_B2   209920
#define SMEM_TOT 210944

#define LDSM_X4(r0,r1,r2,r3, addr) \
    asm volatile("ldmatrix.sync.aligned.m8n8.x4.shared.b16 {%0,%1,%2,%3}, [%4];" \
        : "=r"(r0), "=r"(r1), "=r"(r2), "=r"(r3) : "r"(addr))

#define MMA_BF16(d, a0,a1,a2,a3, b0,b1) \
    asm volatile("mma.sync.aligned.m16n8k16.row.col.f32.bf16.bf16.f32 " \
        "{%0,%1,%2,%3}, {%4,%5,%6,%7}, {%8,%9}, {%0,%1,%2,%3};" \
        : "+f"((d)[0]), "+f"((d)[1]), "+f"((d)[2]), "+f"((d)[3]) \
        : "r"(a0), "r"(a1), "r"(a2), "r"(a3), "r"(b0), "r"(b1))

__global__ void __launch_bounds__(256, 1) k_mlp(const float* __restrict__ b1,
                                                const float* __restrict__ b2,
                                                float* __restrict__ out){
    extern __shared__ char smc[];
    uint32_t sb = smem_u32(smc);
    int tid = threadIdx.x, lane = tid & 31, wid = tid >> 5;
    int wm = wid >> 2, wn = wid & 3;       // 2 x 4 warp grid
    int row0 = blockIdx.x * 128;
    int q = lane & 7, t = lane >> 3;
    int g = lane >> 2, tq = lane & 3;

    ((float*)(smc + SB_B1))[tid] = b1[tid];
    ((float*)(smc + SB_B2))[tid] = b2[tid];

    for (int i = tid; i < 256*8; i += 256){
        int r = i >> 3, j = i & 7;
        *(uint4*)(smc + SB_W1HI + r*144 + j*16) = *(const uint4*)(g_W1hi + (size_t)r*64 + j*8);
        *(uint4*)(smc + SB_W1LO + r*144 + j*16) = *(const uint4*)(g_W1lo + (size_t)r*64 + j*8);
    }
    for (int i = tid; i < 128*8; i += 256){
        int r = i >> 3, j = i & 7;
        *(uint4*)(smc + SB_EHI + r*144 + j*16) = *(const uint4*)(g_Ehi + (size_t)(row0+r)*64 + j*8);
        *(uint4*)(smc + SB_ELO + r*144 + j*16) = *(const uint4*)(g_Elo + (size_t)(row0+r)*64 + j*8);
    }
    __syncthreads();

    float acc[4][8][4];
    #pragma unroll
    for (int mi = 0; mi < 4; mi++)
        #pragma unroll
        for (int ni = 0; ni < 8; ni++)
            #pragma unroll
            for (int e = 0; e < 4; e++) acc[mi][ni][e] = 0.0f;

    uint32_t laneA144 = (uint32_t)(((t & 1)*8 + q)*144 + (t >> 1)*16);
    uint32_t laneA528 = (uint32_t)(((t & 1)*8 + q)*528 + (t >> 1)*16);
    uint32_t laneB144 = (uint32_t)(((t >> 1)*8 + q)*144 + (t & 1)*16);

    // ---- stage 1: K = 64 ----
    {
        uint32_t aHi = sb + SB_EHI  + (uint32_t)(wm*64)*144 + laneA144;
        uint32_t aLo = sb + SB_ELO  + (uint32_t)(wm*64)*144 + laneA144;
        uint32_t bHi = sb + SB_W1HI + (uint32_t)(wn*64)*144 + laneB144;
        uint32_t bLo = sb + SB_W1LO + (uint32_t)(wn*64)*144 + laneB144;
        for (int kk = 0; kk < 4; kk++){
            uint32_t k0b = kk*32;
            uint32_t bh[8][2], bl[8][2];
            #pragma unroll
            for (int nj = 0; nj < 4; nj++){
                LDSM_X4(bh[2*nj][0], bh[2*nj][1], bh[2*nj+1][0], bh[2*nj+1][1],
                        bHi + (uint32_t)(nj*16)*144 + k0b);
                LDSM_X4(bl[2*nj][0], bl[2*nj][1], bl[2*nj+1][0], bl[2*nj+1][1],
                        bLo + (uint32_t)(nj*16)*144 + k0b);
            }
            #pragma unroll
            for (int mi = 0; mi < 4; mi++){
                uint32_t a0,a1,a2,a3;
                LDSM_X4(a0,a1,a2,a3, aHi + (uint32_t)(mi*16)*144 + k0b);
                #pragma unroll
                for (int ni = 0; ni < 8; ni++){
                    MMA_BF16(acc[mi][ni], a0,a1,a2,a3, bh[ni][0], bh[ni][1]);
                    MMA_BF16(acc[mi][ni], a0,a1,a2,a3, bl[ni][0], bl[ni][1]);
                }
                LDSM_X4(a0,a1,a2,a3, aLo + (uint32_t)(mi*16)*144 + k0b);
                #pragma unroll
                for (int ni = 0; ni < 8; ni++)
                    MMA_BF16(acc[mi][ni], a0,a1,a2,a3, bh[ni][0], bh[ni][1]);
            }
        }
    }
    __syncthreads();   // all warps done reading W1/E before H overwrites the region

    // ---- epilogue 1: relu(acc + b1) -> H hi/lo in smem, zero acc ----
    {
        const float* b1s = (const float*)(smc + SB_B1);
        #pragma unroll
        for (int mi = 0; mi < 4; mi++){
            int r0 = wm*64 + mi*16 + g;
            #pragma unroll
            for (int ni = 0; ni < 8; ni++){
                int col = wn*64 + ni*8 + tq*2;
                float bc0 = b1s[col], bc1 = b1s[col+1];
                #pragma unroll
                for (int half = 0; half < 2; half++){
                    int r = r0 + half*8;
                    float v0 = fmaxf(acc[mi][ni][half*2+0] + bc0, 0.0f);
                    float v1 = fmaxf(acc[mi][ni][half*2+1] + bc1, 0.0f);
                    __nv_bfloat16 h0 = __float2bfloat16(v0);
                    __nv_bfloat16 h1 = __float2bfloat16(v1);
                    __nv_bfloat162 hp; hp.x = h0; hp.y = h1;
                    __nv_bfloat162 lp;
                    lp.x = __float2bfloat16(v0 - __bfloat162float(h0));
                    lp.y = __float2bfloat16(v1 - __bfloat162float(h1));
                    *(__nv_bfloat162*)(smc + SB_HHI + r*528 + col*2) = hp;
                    *(__nv_bfloat162*)(smc + SB_HLO + r*528 + col*2) = lp;
                    acc[mi][ni][half*2+0] = 0.0f;
                    acc[mi][ni][half*2+1] = 0.0f;
                }
            }
        }
    }

    // ---- stage 2: K = 256 in 4 chunks; A = H (smem), B = W2 (streamed) ----
    {
        uint32_t aHi = sb + SB_HHI + (uint32_t)(wm*64)*528 + laneA528;
        uint32_t aLo = sb + SB_HLO + (uint32_t)(wm*64)*528 + laneA528;
        uint32_t bHi = sb + SB_W2HI + (uint32_t)(wn*64)*144 + laneB144;
        uint32_t bLo = sb + SB_W2LO + (uint32_t)(wn*64)*144 + laneB144;
        for (int kc = 0; kc < 4; kc++){
            __syncthreads();
            for (int i = tid; i < 256*8; i += 256){
                int r = i >> 3, j = i & 7;
                *(uint4*)(smc + SB_W2HI + r*144 + j*16) =
                    *(const uint4*)(g_W2hi + (size_t)r*256 + kc*64 + j*8);
                *(uint4*)(smc + SB_W2LO + r*144 + j*16) =
                    *(const uint4*)(g_W2lo + (size_t)r*256 + kc*64 + j*8);
            }
            __syncthreads();
            for (int kk = 0; kk < 4; kk++){
                uint32_t k0A = (uint32_t)(kc*64 + kk*16)*2;
                uint32_t k0B = kk*32;
                uint32_t bh[8][2], bl[8][2];
                #pragma unroll
                for (int nj = 0; nj < 4; nj++){
                    LDSM_X4(bh[2*nj][0], bh[2*nj][1], bh[2*nj+1][0], bh[2*nj+1][1],
                            bHi + (uint32_t)(nj*16)*144 + k0B);
                    LDSM_X4(bl[2*nj][0], bl[2*nj][1], bl[2*nj+1][0], bl[2*nj+1][1],
                            bLo + (uint32_t)(nj*16)*144 + k0B);
                }
                #pragma unroll
                for (int mi = 0; mi < 4; mi++){
                    uint32_t a0,a1,a2,a3;
                    LDSM_X4(a0,a1,a2,a3, aHi + (uint32_t)(mi*16)*528 + k0A);
                    #pragma unroll
                    for (int ni = 0; ni < 8; ni++){
                        MMA_BF16(acc[mi][ni], a0,a1,a2,a3, bh[ni][0], bh[ni][1]);
                        MMA_BF16(acc[mi][ni], a0,a1,a2,a3, bl[ni][0], bl[ni][1]);
                    }
                    LDSM_X4(a0,a1,a2,a3, aLo + (uint32_t)(mi*16)*528 + k0A);
                    #pragma unroll
                    for (int ni = 0; ni < 8; ni++)
                        MMA_BF16(acc[mi][ni], a0,a1,a2,a3, bh[ni][0], bh[ni][1]);
                }
            }
        }
    }

    // ---- epilogue 2: out = acc + b2 ----
    {
        const float* b2s = (const float*)(smc + SB_B2);
        #pragma unroll
        for (int mi = 0; mi < 4; mi++){
            int r0 = row0 + wm*64 + mi*16 + g;
            #pragma unroll
            for (int ni = 0; ni < 8; ni++){
                int col = wn*64 + ni*8 + tq*2;
                float bc0 = b2s[col], bc1 = b2s[col+1];
                #pragma unroll
                for (int half = 0; half < 2; half++){
                    int r = r0 + half*8;
                    float2 o;
                    o.x = acc[mi][ni][half*2+0] + bc0;
                    o.y = acc[mi][ni][half*2+1] + bc1;
                    *(float2*)&out[(size_t)r*256 + col] = o;
                }
            }
        }
    }
}

// ---------------- launcher ----------------
extern "C" void kernel_launch(void* const* d_in, const int* in_sizes, int n_in,
                              void* d_out, int out_size){
    const float* rgb  = (const float*)d_in[0];
    const float* f1   = (const float*)d_in[1];
    const float* f2   = (const float*)d_in[2];
    const float* f3   = (const float*)d_in[3];
    const float* pos  = (const float*)d_in[4];
    const float* pdir = (const float*)d_in[5];
    const float* W1   = (const float*)d_in[6];
    const float* b1   = (const float*)d_in[7];
    const float* W2   = (const float*)d_in[8];
    const float* b2   = (const float*)d_in[9];
    float* out = (float*)d_out;

    cudaFuncSetAttribute(k_mlp, cudaFuncAttributeMaxDynamicSharedMemorySize, SMEM_TOT);

    k_init_cvt<<<256, 256>>>(W1, W2);            // init + weight convert fused
    k_minmax  <<<256, 256>>>(pos);
    k_bin     <<<NP/256, 256>>>(pos);            // direct bucket scatter
    k_select  <<<VN*32/256, 256>>>(pos);         // warp/voxel: key sort + c-bounded sum
    k_gather  <<<VN/4, 128>>>(rgb, f1, f2, f3, pos, pdir, out);
    k_mlp     <<<VN/128, 256, SMEM_TOT>>>(b1, b2, out);
}